// round 15
// baseline (speedup 1.0000x reference)
#include <cuda_runtime.h>
#include <cuda_fp16.h>
#include <math_constants.h>
#include <cstdint>
#include <cstddef>

#define C_IN  64
#define F_OUT 128
#define NPOS  9
#define HH    128
#define WWID  128
#define NB    16
#define NPIX  (NB*HH*WWID)

__device__ __half g_xh[(size_t)NPIX * C_IN];
__device__ __half g_W[NPOS * F_OUT * C_IN];   // [kpos][f][c]

// ---------------- kernel 1: weights (blocks 0..31) + x->fp16 (rest) -------
__global__ void prep_kernel(const float* __restrict__ x,
                            const float* __restrict__ D,
                            const float* __restrict__ u,
                            const float* __restrict__ kern) {
    const int bx = blockIdx.x, tid = threadIdx.x;
    if (bx < 32) {
        int t = bx * 256 + tid;
        if (t >= F_OUT * C_IN) return;
        const float* Dp = D + t * NPOS;
        const float* up = u + t * NPOS;
        float pert[NPOS];
#pragma unroll
        for (int n = 0; n < NPOS; ++n) {
            float g = -0.001f * logf(-logf(up[n] + 1e-20f) + 1e-20f);
            pert[n] = Dp[n] + g;
        }
        unsigned sel = 0;
#pragma unroll
        for (int j = 0; j < 4; ++j) {
            int bi = 0; float bv = -CUDART_INF_F;
#pragma unroll
            for (int n = 0; n < NPOS; ++n) {
                bool tk = (sel >> n) & 1u;
                if (!tk && pert[n] > bv) { bv = pert[n]; bi = n; }
            }
            sel |= (1u << bi);
        }
        const float* kp = kern + t * NPOS;
#pragma unroll
        for (int n = 0; n < NPOS; ++n) {
            int p = t * NPOS + n;              // flat index in (3,3,64,128)
            float w = kp[n];
            float s = (w > 0.f) ? 1.f : ((w < 0.f) ? -1.f : 0.f);
            float v = ((sel >> n) & 1u) ? s : 0.f;
            int f = p & 127, c = (p >> 7) & 63, kpos = p >> 13;
            g_W[kpos * 8192 + f * 64 + c] = __float2half_rn(v);
        }
    } else {
        size_t i = (size_t)(bx - 32) * 256 + tid;     // float4 group
        float4 v = reinterpret_cast<const float4*>(x)[i];
        unsigned h0 = __half_as_ushort(__float2half_rn(v.x));
        unsigned h1 = __half_as_ushort(__float2half_rn(v.y));
        unsigned h2 = __half_as_ushort(__float2half_rn(v.z));
        unsigned h3 = __half_as_ushort(__float2half_rn(v.w));
        uint2 ph = make_uint2(h0 | (h1 << 16), h2 | (h3 << 16));
        reinterpret_cast<uint2*>(g_xh)[i] = ph;
    }
}

// ---------------- helpers ----------------
__device__ __forceinline__ uint32_t s2u(const void* p) {
    uint32_t a;
    asm("{ .reg .u64 t; cvta.to.shared.u64 t, %1; cvt.u32.u64 %0, t; }"
        : "=r"(a) : "l"(p));
    return a;
}
__device__ __forceinline__ void cpa16(uint32_t dst, const void* src) {
    asm volatile("cp.async.cg.shared.global [%0], [%1], 16;"
                 :: "r"(dst), "l"(src) : "memory");
}
__device__ __forceinline__ void st16z(uint32_t dst) {
    asm volatile("st.shared.v4.b32 [%0], {%1,%1,%1,%1};"
                 :: "r"(dst), "r"(0) : "memory");
}
#define CP_COMMIT() asm volatile("cp.async.commit_group;" ::: "memory")
#define CP_WAIT1()  asm volatile("cp.async.wait_group 1;" ::: "memory")

__device__ __forceinline__ void ldsm4(uint32_t* r, uint32_t addr) {
    asm volatile("ldmatrix.sync.aligned.m8n8.x4.shared.b16 {%0,%1,%2,%3}, [%4];"
                 : "=r"(r[0]), "=r"(r[1]), "=r"(r[2]), "=r"(r[3]) : "r"(addr));
}
__device__ __forceinline__ void mma16816(float* d, const uint32_t* a,
                                         uint32_t b0, uint32_t b1) {
    asm volatile(
        "mma.sync.aligned.m16n8k16.row.col.f32.f16.f16.f32 "
        "{%0,%1,%2,%3}, {%4,%5,%6,%7}, {%8,%9}, {%0,%1,%2,%3};"
        : "+f"(d[0]), "+f"(d[1]), "+f"(d[2]), "+f"(d[3])
        : "r"(a[0]), "r"(a[1]), "r"(a[2]), "r"(a[3]), "r"(b0), "r"(b1));
}

// smem layout
#define A_STRIDE 144                    // bytes per A row (64 fp16 + 16B pad)
#define A_ROWS   130                    // w_in -1..128 (rows 0,129 zero)
#define A_BUF    (A_ROWS * A_STRIDE)    // 18720
#define B_STRIDE 144
#define B_BUF    (128 * B_STRIDE)       // 18432
#define SM_BOFF  (2 * A_BUF)            // 37440
#define SMEM_SZ  (SM_BOFF + 3 * B_BUF)  // 92736 (x2 = 185472 <= 228KB/SM)

// Load A tile for dh: rows 1..128 <- w_in 0..127; rows 0,129 zeroed.
__device__ __forceinline__ void loadA(uint32_t abase, const __half* arr,
                                      int h, int dh, int tid) {
    const int hin = h + dh;
    if ((unsigned)hin < 128u) {
        if (tid < 18) {
            uint32_t adr = abase + ((tid < 9) ? 0u : (uint32_t)(129 * A_STRIDE))
                         + (uint32_t)(tid % 9) * 16u;
            st16z(adr);
        }
        const __half* rowp = arr + (size_t)hin * (WWID * C_IN);
#pragma unroll
        for (int i = 0; i < 4; ++i) {
            int idx = i * 256 + tid;           // 0..1023
            int r = idx >> 3, c = idx & 7;
            cpa16(abase + (uint32_t)(r + 1) * A_STRIDE + c * 16,
                  rowp + r * C_IN + c * 8);
        }
    } else {
#pragma unroll
        for (int i = 0; i < 5; ++i) {
            int idx = i * 256 + tid;
            if (idx < (A_BUF / 16)) st16z(abase + idx * 16);
        }
    }
}
__device__ __forceinline__ void loadB(uint32_t bbase, int kpos, int tid) {
    const __half* w = g_W + kpos * 8192;
#pragma unroll
    for (int i = 0; i < 4; ++i) {
        int idx = i * 256 + tid;               // 0..1023
        int f = idx >> 3, c = idx & 7;
        cpa16(bbase + (uint32_t)f * B_STRIDE + c * 16, w + f * 64 + c * 8);
    }
}

// Fragment loaders (per warp, 64x32 tile)
__device__ __forceinline__ void loadBfrag(uint32_t* bf, uint32_t bB, int ks) {
#pragma unroll
    for (int p2 = 0; p2 < 2; ++p2) {
        uint32_t r[4];
        ldsm4(r, bB + p2 * 16 * B_STRIDE + ks * 32);
        bf[p2 * 2]         = r[0];   // b0 even
        bf[4 + p2 * 2]     = r[1];   // b1 even
        bf[p2 * 2 + 1]     = r[2];   // b0 odd
        bf[4 + p2 * 2 + 1] = r[3];   // b1 odd
    }
}
__device__ __forceinline__ void loadAfrag(uint32_t* af, uint32_t aB, int ks) {
#pragma unroll
    for (int mi = 0; mi < 4; ++mi)
        ldsm4(af + mi * 4, aB + mi * 16 * A_STRIDE + ks * 32);
}

// ---------------- kernel 2: mma.sync conv (cross-iter A warmup) -----------
__global__ void __launch_bounds__(256, 2)
conv_mma_kernel(const float* __restrict__ bias, float* __restrict__ out) {
    extern __shared__ char smem[];
    const uint32_t sb = s2u(smem);
    const int tid = threadIdx.x, wid = tid >> 5, l = tid & 31;
    const int m0w = (wid & 1) * 64, n0w = (wid >> 1) * 32;
    const int bx = blockIdx.x;
    const int n = bx >> 7, h = bx & 127;

    const __half* xh = g_xh + (size_t)n * (HH * WWID * C_IN);

    float acc[4][4][4];
#pragma unroll
    for (int mi = 0; mi < 4; ++mi)
#pragma unroll
        for (int ni = 0; ni < 4; ++ni)
#pragma unroll
            for (int c = 0; c < 4; ++c) acc[mi][ni][c] = 0.f;

    const uint32_t arow = (uint32_t)(m0w + (l & 15) + 1) * A_STRIDE + (l >> 4) * 16;
    const uint32_t brow = (uint32_t)(n0w + ((l >> 4) << 3) + (l & 7)) * B_STRIDE
                        + ((l >> 3) & 1) * 16;

    // prologue: G0 = A(dh=-1)->abuf0 + B0->bbuf0 ; G1 = B1->bbuf1
    loadA(sb, xh, h, -1, tid);
    loadB(sb + SM_BOFF, 0, tid);
    CP_COMMIT();
    loadB(sb + SM_BOFF + B_BUF, 1, tid);
    CP_COMMIT();

    uint32_t af[2][16];                        // persists across iterations

#pragma unroll 1
    for (int di = 0; di < 3; ++di) {
        const uint32_t aBase = sb + (di & 1) * A_BUF + arow;
#pragma unroll
        for (int j = 0; j < 3; ++j) {           // dw = j-1, k = di*3+j
            CP_WAIT1();                          // this k's A + B resident
            __syncthreads();                     // visibility + reuse safety

            const uint32_t aB = aBase + (j - 1) * A_STRIDE;
            const uint32_t bB = sb + SM_BOFF + j * B_BUF + brow;

            // ks=0 warmup: B always; A only on the very first iteration
            uint32_t bf[2][8];
            loadBfrag(bf[0], bB, 0);
            if (di == 0 && j == 0) loadAfrag(af[0], aB, 0);

            // issue future global loads (B: +2 iterations; A: +3)
            if (di < 2 || j == 0)
                loadB(sb + SM_BOFF + ((j + 2) % 3) * B_BUF, di * 3 + j + 2, tid);
            if (j == 0 && di < 2)
                loadA(sb + ((di + 1) & 1) * A_BUF, xh, h, di, tid);
            CP_COMMIT();

#pragma unroll
            for (int ks = 0; ks < 4; ++ks) {
                const int cur = ks & 1, nxt = cur ^ 1;
                if (ks < 3) {                    // prefetch next fragments
                    loadBfrag(bf[nxt], bB, ks + 1);
                    loadAfrag(af[nxt], aB, ks + 1);
                } else {
                    // ks==3: af[0] is dead -> warm next iteration's ks=0 A
                    if (j < 2)
                        loadAfrag(af[0], aBase + j * A_STRIDE, 0);
                    else if (di < 2)
                        loadAfrag(af[0],
                                  sb + ((di + 1) & 1) * A_BUF + arow - A_STRIDE, 0);
                }
#pragma unroll
                for (int mi = 0; mi < 4; ++mi)
#pragma unroll
                    for (int ni = 0; ni < 4; ++ni)
                        mma16816(acc[mi][ni], &af[cur][mi * 4],
                                 bf[cur][ni], bf[cur][4 + ni]);
            }
        }
    }

    // epilogue: +bias, ReLU, store
#pragma unroll
    for (int mi = 0; mi < 4; ++mi) {
#pragma unroll
        for (int ni = 0; ni < 4; ++ni) {
            int col = n0w + ni * 8 + (l & 3) * 2;
            float2 bb = *reinterpret_cast<const float2*>(bias + col);
            size_t pix = (size_t)bx * 128 + m0w + mi * 16 + (l >> 2);
            float2 o0, o1;
            o0.x = fmaxf(acc[mi][ni][0] + bb.x, 0.f);
            o0.y = fmaxf(acc[mi][ni][1] + bb.y, 0.f);
            o1.x = fmaxf(acc[mi][ni][2] + bb.x, 0.f);
            o1.y = fmaxf(acc[mi][ni][3] + bb.y, 0.f);
            *reinterpret_cast<float2*>(out + pix * F_OUT + col) = o0;
            *reinterpret_cast<float2*>(out + (pix + 8) * F_OUT + col) = o1;
        }
    }
}

// ---------------- launch ----------------
extern "C" void kernel_launch(void* const* d_in, const int* in_sizes, int n_in,
                              void* d_out, int out_size) {
    const float* x    = (const float*)d_in[0];
    const float* kern = (const float*)d_in[1];
    const float* b    = (const float*)d_in[2];
    const float* D    = (const float*)d_in[3];
    const float* u    = (const float*)d_in[4];
    float* out = (float*)d_out;

    static int smem_set = 0;
    if (!smem_set) {
        cudaFuncSetAttribute(conv_mma_kernel,
                             cudaFuncAttributeMaxDynamicSharedMemorySize, SMEM_SZ);
        smem_set = 1;
    }

    prep_kernel<<<32 + (NPIX * C_IN / 4) / 256, 256>>>(x, D, u, kern);
    conv_mma_kernel<<<NB * HH, 256, SMEM_SZ>>>(b, out);
}

// round 16
// speedup vs baseline: 1.0611x; 1.0611x over previous
#include <cuda_runtime.h>
#include <cuda_fp16.h>
#include <math_constants.h>
#include <cstdint>
#include <cstddef>

#define C_IN  64
#define F_OUT 128
#define NPOS  9
#define HH    128
#define WWID  128
#define NB    16
#define NPIX  (NB*HH*WWID)

__device__ __half g_xh[(size_t)NPIX * C_IN];
__device__ __half g_W[NPOS * F_OUT * C_IN];   // [kpos][f][c]

// ---------------- kernel 1: weights (blocks 0..31) + x->fp16 (rest) -------
// Convert blocks process 8 floats (32B) per thread.
__global__ void prep_kernel(const float* __restrict__ x,
                            const float* __restrict__ D,
                            const float* __restrict__ u,
                            const float* __restrict__ kern) {
    const int bx = blockIdx.x, tid = threadIdx.x;
    if (bx < 32) {
        int t = bx * 256 + tid;
        if (t >= F_OUT * C_IN) return;
        const float* Dp = D + t * NPOS;
        const float* up = u + t * NPOS;
        float pert[NPOS];
#pragma unroll
        for (int n = 0; n < NPOS; ++n) {
            float g = -0.001f * logf(-logf(up[n] + 1e-20f) + 1e-20f);
            pert[n] = Dp[n] + g;
        }
        unsigned sel = 0;
#pragma unroll
        for (int j = 0; j < 4; ++j) {
            int bi = 0; float bv = -CUDART_INF_F;
#pragma unroll
            for (int n = 0; n < NPOS; ++n) {
                bool tk = (sel >> n) & 1u;
                if (!tk && pert[n] > bv) { bv = pert[n]; bi = n; }
            }
            sel |= (1u << bi);
        }
        const float* kp = kern + t * NPOS;
#pragma unroll
        for (int n = 0; n < NPOS; ++n) {
            int p = t * NPOS + n;              // flat index in (3,3,64,128)
            float w = kp[n];
            float s = (w > 0.f) ? 1.f : ((w < 0.f) ? -1.f : 0.f);
            float v = ((sel >> n) & 1u) ? s : 0.f;
            int f = p & 127, c = (p >> 7) & 63, kpos = p >> 13;
            g_W[kpos * 8192 + f * 64 + c] = __float2half_rn(v);
        }
    } else {
        size_t i = ((size_t)(bx - 32) * 256 + tid) * 2;   // two float4 groups
#pragma unroll
        for (int q = 0; q < 2; ++q) {
            float4 v = reinterpret_cast<const float4*>(x)[i + q];
            unsigned h0 = __half_as_ushort(__float2half_rn(v.x));
            unsigned h1 = __half_as_ushort(__float2half_rn(v.y));
            unsigned h2 = __half_as_ushort(__float2half_rn(v.z));
            unsigned h3 = __half_as_ushort(__float2half_rn(v.w));
            uint2 ph = make_uint2(h0 | (h1 << 16), h2 | (h3 << 16));
            reinterpret_cast<uint2*>(g_xh)[i + q] = ph;
        }
    }
}

// ---------------- helpers ----------------
__device__ __forceinline__ uint32_t s2u(const void* p) {
    uint32_t a;
    asm("{ .reg .u64 t; cvta.to.shared.u64 t, %1; cvt.u32.u64 %0, t; }"
        : "=r"(a) : "l"(p));
    return a;
}
__device__ __forceinline__ void cpa16(uint32_t dst, const void* src) {
    asm volatile("cp.async.cg.shared.global [%0], [%1], 16;"
                 :: "r"(dst), "l"(src) : "memory");
}
__device__ __forceinline__ void st16z(uint32_t dst) {
    asm volatile("st.shared.v4.b32 [%0], {%1,%1,%1,%1};"
                 :: "r"(dst), "r"(0) : "memory");
}
#define CP_COMMIT() asm volatile("cp.async.commit_group;" ::: "memory")
#define CP_WAIT1()  asm volatile("cp.async.wait_group 1;" ::: "memory")

__device__ __forceinline__ void ldsm4(uint32_t* r, uint32_t addr) {
    asm volatile("ldmatrix.sync.aligned.m8n8.x4.shared.b16 {%0,%1,%2,%3}, [%4];"
                 : "=r"(r[0]), "=r"(r[1]), "=r"(r[2]), "=r"(r[3]) : "r"(addr));
}
__device__ __forceinline__ void mma16816(float* d, const uint32_t* a,
                                         uint32_t b0, uint32_t b1) {
    asm volatile(
        "mma.sync.aligned.m16n8k16.row.col.f32.f16.f16.f32 "
        "{%0,%1,%2,%3}, {%4,%5,%6,%7}, {%8,%9}, {%0,%1,%2,%3};"
        : "+f"(d[0]), "+f"(d[1]), "+f"(d[2]), "+f"(d[3])
        : "r"(a[0]), "r"(a[1]), "r"(a[2]), "r"(a[3]), "r"(b0), "r"(b1));
}

// smem layout
#define A_STRIDE 144                    // bytes per A row (64 fp16 + 16B pad)
#define A_ROWS   130                    // w_in -1..128 (rows 0,129 zero)
#define A_BUF    (A_ROWS * A_STRIDE)    // 18720
#define B_STRIDE 144
#define B_BUF    (128 * B_STRIDE)       // 18432
#define SM_BOFF  (2 * A_BUF)            // 37440
#define SMEM_SZ  (SM_BOFF + 3 * B_BUF)  // 92736 (x2 = 185472 <= 228KB/SM)

// Load A tile for dh: rows 1..128 <- w_in 0..127; rows 0,129 zeroed.
__device__ __forceinline__ void loadA(uint32_t abase, const __half* arr,
                                      int h, int dh, int tid) {
    const int hin = h + dh;
    if ((unsigned)hin < 128u) {
        if (tid < 18) {
            uint32_t adr = abase + ((tid < 9) ? 0u : (uint32_t)(129 * A_STRIDE))
                         + (uint32_t)(tid % 9) * 16u;
            st16z(adr);
        }
        const __half* rowp = arr + (size_t)hin * (WWID * C_IN);
#pragma unroll
        for (int i = 0; i < 4; ++i) {
            int idx = i * 256 + tid;           // 0..1023
            int r = idx >> 3, c = idx & 7;
            cpa16(abase + (uint32_t)(r + 1) * A_STRIDE + c * 16,
                  rowp + r * C_IN + c * 8);
        }
    } else {
#pragma unroll
        for (int i = 0; i < 5; ++i) {
            int idx = i * 256 + tid;
            if (idx < (A_BUF / 16)) st16z(abase + idx * 16);
        }
    }
}
__device__ __forceinline__ void loadB(uint32_t bbase, int kpos, int tid) {
    const __half* w = g_W + kpos * 8192;
#pragma unroll
    for (int i = 0; i < 4; ++i) {
        int idx = i * 256 + tid;               // 0..1023
        int f = idx >> 3, c = idx & 7;
        cpa16(bbase + (uint32_t)f * B_STRIDE + c * 16, w + f * 64 + c * 8);
    }
}

// Fragment loaders (per warp, 64x32 tile)
__device__ __forceinline__ void loadBfrag(uint32_t* bf, uint32_t bB, int ks) {
#pragma unroll
    for (int p2 = 0; p2 < 2; ++p2) {
        uint32_t r[4];
        ldsm4(r, bB + p2 * 16 * B_STRIDE + ks * 32);
        bf[p2 * 2]         = r[0];   // b0 even
        bf[4 + p2 * 2]     = r[1];   // b1 even
        bf[p2 * 2 + 1]     = r[2];   // b0 odd
        bf[4 + p2 * 2 + 1] = r[3];   // b1 odd
    }
}
__device__ __forceinline__ void loadAfrag(uint32_t* af, uint32_t aB, int ks) {
#pragma unroll
    for (int mi = 0; mi < 4; ++mi)
        ldsm4(af + mi * 4, aB + mi * 16 * A_STRIDE + ks * 32);
}

// ---------------- kernel 2: mma.sync conv (R14 engine, unchanged) ---------
__global__ void __launch_bounds__(256, 2)
conv_mma_kernel(const float* __restrict__ bias, float* __restrict__ out) {
    extern __shared__ char smem[];
    const uint32_t sb = s2u(smem);
    const int tid = threadIdx.x, wid = tid >> 5, l = tid & 31;
    const int m0w = (wid & 1) * 64, n0w = (wid >> 1) * 32;
    const int bx = blockIdx.x;
    const int n = bx >> 7, h = bx & 127;

    const __half* xh = g_xh + (size_t)n * (HH * WWID * C_IN);

    float acc[4][4][4];
#pragma unroll
    for (int mi = 0; mi < 4; ++mi)
#pragma unroll
        for (int ni = 0; ni < 4; ++ni)
#pragma unroll
            for (int c = 0; c < 4; ++c) acc[mi][ni][c] = 0.f;

    const uint32_t arow = (uint32_t)(m0w + (l & 15) + 1) * A_STRIDE + (l >> 4) * 16;
    const uint32_t brow = (uint32_t)(n0w + ((l >> 4) << 3) + (l & 7)) * B_STRIDE
                        + ((l >> 3) & 1) * 16;

    // prologue: G0 = A(dh=-1)->abuf0 + B0->bbuf0 ; G1 = B1->bbuf1
    loadA(sb, xh, h, -1, tid);
    loadB(sb + SM_BOFF, 0, tid);
    CP_COMMIT();
    loadB(sb + SM_BOFF + B_BUF, 1, tid);
    CP_COMMIT();

#pragma unroll 1
    for (int di = 0; di < 3; ++di) {
        const uint32_t aBase = sb + (di & 1) * A_BUF + arow;
#pragma unroll
        for (int j = 0; j < 3; ++j) {           // dw = j-1, k = di*3+j
            CP_WAIT1();                          // this k's A + B resident
            __syncthreads();                     // visibility + reuse safety

            const uint32_t aB = aBase + (j - 1) * A_STRIDE;
            const uint32_t bB = sb + SM_BOFF + j * B_BUF + brow;

            // early fragment warmup for ks=0
            uint32_t bf[2][8], af[2][16];
            loadBfrag(bf[0], bB, 0);
            loadAfrag(af[0], aB, 0);

            // issue future global loads (B: +2 iterations; A: +3)
            if (di < 2 || j == 0)
                loadB(sb + SM_BOFF + ((j + 2) % 3) * B_BUF, di * 3 + j + 2, tid);
            if (j == 0 && di < 2)
                loadA(sb + ((di + 1) & 1) * A_BUF, xh, h, di, tid);
            CP_COMMIT();

#pragma unroll
            for (int ks = 0; ks < 4; ++ks) {
                const int cur = ks & 1, nxt = cur ^ 1;
                if (ks < 3) {                    // prefetch next fragments
                    loadBfrag(bf[nxt], bB, ks + 1);
                    loadAfrag(af[nxt], aB, ks + 1);
                }
#pragma unroll
                for (int mi = 0; mi < 4; ++mi)
#pragma unroll
                    for (int ni = 0; ni < 4; ++ni)
                        mma16816(acc[mi][ni], &af[cur][mi * 4],
                                 bf[cur][ni], bf[cur][4 + ni]);
            }
        }
    }

    // epilogue: +bias, ReLU, store
    float2 bb[4];
#pragma unroll
    for (int ni = 0; ni < 4; ++ni) {
        int col = n0w + ni * 8 + (l & 3) * 2;
        bb[ni] = *reinterpret_cast<const float2*>(bias + col);
    }
#pragma unroll
    for (int mi = 0; mi < 4; ++mi) {
#pragma unroll
        for (int ni = 0; ni < 4; ++ni) {
            int col = n0w + ni * 8 + (l & 3) * 2;
            size_t pix = (size_t)bx * 128 + m0w + mi * 16 + (l >> 2);
            float2 o0, o1;
            o0.x = fmaxf(acc[mi][ni][0] + bb[ni].x, 0.f);
            o0.y = fmaxf(acc[mi][ni][1] + bb[ni].y, 0.f);
            o1.x = fmaxf(acc[mi][ni][2] + bb[ni].x, 0.f);
            o1.y = fmaxf(acc[mi][ni][3] + bb[ni].y, 0.f);
            *reinterpret_cast<float2*>(out + pix * F_OUT + col) = o0;
            *reinterpret_cast<float2*>(out + (pix + 8) * F_OUT + col) = o1;
        }
    }
}

// ---------------- launch ----------------
extern "C" void kernel_launch(void* const* d_in, const int* in_sizes, int n_in,
                              void* d_out, int out_size) {
    const float* x    = (const float*)d_in[0];
    const float* kern = (const float*)d_in[1];
    const float* b    = (const float*)d_in[2];
    const float* D    = (const float*)d_in[3];
    const float* u    = (const float*)d_in[4];
    float* out = (float*)d_out;

    static int smem_set = 0;
    if (!smem_set) {
        cudaFuncSetAttribute(conv_mma_kernel,
                             cudaFuncAttributeMaxDynamicSharedMemorySize, SMEM_SZ);
        smem_set = 1;
    }

    prep_kernel<<<32 + (NPIX * C_IN / 8) / 256, 256>>>(x, D, u, kern);
    conv_mma_kernel<<<NB * HH, 256, SMEM_SZ>>>(b, out);
}

// round 17
// speedup vs baseline: 1.0771x; 1.0151x over previous
#include <cuda_runtime.h>
#include <cuda_fp16.h>
#include <math_constants.h>
#include <cstdint>
#include <cstddef>

#define C_IN  64
#define F_OUT 128
#define NPOS  9
#define HH    128
#define WWID  128
#define NB    16
#define NPIX  (NB*HH*WWID)

__device__ __half g_xh[(size_t)NPIX * C_IN];
__device__ __half g_W[NPOS * F_OUT * C_IN];   // [kpos][f][c]

// ---------------- kernel 1: weights (blocks 0..31) + x->fp16 (rest) -------
__global__ void prep_kernel(const float* __restrict__ x,
                            const float* __restrict__ D,
                            const float* __restrict__ u,
                            const float* __restrict__ kern) {
    const int bx = blockIdx.x, tid = threadIdx.x;
    if (bx < 32) {
        int t = bx * 256 + tid;
        if (t >= F_OUT * C_IN) return;
        const float* Dp = D + t * NPOS;
        const float* up = u + t * NPOS;
        float pert[NPOS];
#pragma unroll
        for (int n = 0; n < NPOS; ++n) {
            float g = -0.001f * logf(-logf(up[n] + 1e-20f) + 1e-20f);
            pert[n] = Dp[n] + g;
        }
        unsigned sel = 0;
#pragma unroll
        for (int j = 0; j < 4; ++j) {
            int bi = 0; float bv = -CUDART_INF_F;
#pragma unroll
            for (int n = 0; n < NPOS; ++n) {
                bool tk = (sel >> n) & 1u;
                if (!tk && pert[n] > bv) { bv = pert[n]; bi = n; }
            }
            sel |= (1u << bi);
        }
        const float* kp = kern + t * NPOS;
#pragma unroll
        for (int n = 0; n < NPOS; ++n) {
            int p = t * NPOS + n;              // flat index in (3,3,64,128)
            float w = kp[n];
            float s = (w > 0.f) ? 1.f : ((w < 0.f) ? -1.f : 0.f);
            float v = ((sel >> n) & 1u) ? s : 0.f;
            int f = p & 127, c = (p >> 7) & 63, kpos = p >> 13;
            g_W[kpos * 8192 + f * 64 + c] = __float2half_rn(v);
        }
    } else {
        size_t i = ((size_t)(bx - 32) * 256 + tid) * 2;   // two float4 groups
        unsigned hh[8];
#pragma unroll
        for (int q = 0; q < 2; ++q) {
            float4 v = reinterpret_cast<const float4*>(x)[i + q];
            hh[q * 4 + 0] = __half_as_ushort(__float2half_rn(v.x));
            hh[q * 4 + 1] = __half_as_ushort(__float2half_rn(v.y));
            hh[q * 4 + 2] = __half_as_ushort(__float2half_rn(v.z));
            hh[q * 4 + 3] = __half_as_ushort(__float2half_rn(v.w));
        }
        uint4 pk;
        pk.x = hh[0] | (hh[1] << 16);
        pk.y = hh[2] | (hh[3] << 16);
        pk.z = hh[4] | (hh[5] << 16);
        pk.w = hh[6] | (hh[7] << 16);
        reinterpret_cast<uint4*>(g_xh)[i >> 1] = pk;
    }
}

// ---------------- helpers ----------------
__device__ __forceinline__ uint32_t s2u(const void* p) {
    uint32_t a;
    asm("{ .reg .u64 t; cvta.to.shared.u64 t, %1; cvt.u32.u64 %0, t; }"
        : "=r"(a) : "l"(p));
    return a;
}
__device__ __forceinline__ void cpa16(uint32_t dst, const void* src) {
    asm volatile("cp.async.cg.shared.global [%0], [%1], 16;"
                 :: "r"(dst), "l"(src) : "memory");
}
__device__ __forceinline__ void st16z(uint32_t dst) {
    asm volatile("st.shared.v4.b32 [%0], {%1,%1,%1,%1};"
                 :: "r"(dst), "r"(0) : "memory");
}
__device__ __forceinline__ void stg2_cs(float* p, float a, float b) {
    asm volatile("st.global.cs.v2.f32 [%0], {%1,%2};"
                 :: "l"(p), "f"(a), "f"(b) : "memory");
}
#define CP_COMMIT() asm volatile("cp.async.commit_group;" ::: "memory")
#define CP_WAIT1()  asm volatile("cp.async.wait_group 1;" ::: "memory")

__device__ __forceinline__ void ldsm4(uint32_t* r, uint32_t addr) {
    asm volatile("ldmatrix.sync.aligned.m8n8.x4.shared.b16 {%0,%1,%2,%3}, [%4];"
                 : "=r"(r[0]), "=r"(r[1]), "=r"(r[2]), "=r"(r[3]) : "r"(addr));
}
__device__ __forceinline__ void mma16816(float* d, const uint32_t* a,
                                         uint32_t b0, uint32_t b1) {
    asm volatile(
        "mma.sync.aligned.m16n8k16.row.col.f32.f16.f16.f32 "
        "{%0,%1,%2,%3}, {%4,%5,%6,%7}, {%8,%9}, {%0,%1,%2,%3};"
        : "+f"(d[0]), "+f"(d[1]), "+f"(d[2]), "+f"(d[3])
        : "r"(a[0]), "r"(a[1]), "r"(a[2]), "r"(a[3]), "r"(b0), "r"(b1));
}

// smem layout
#define A_STRIDE 144                    // bytes per A row (64 fp16 + 16B pad)
#define A_ROWS   130                    // w_in -1..128 (rows 0,129 zero)
#define A_BUF    (A_ROWS * A_STRIDE)    // 18720
#define B_STRIDE 144
#define B_BUF    (128 * B_STRIDE)       // 18432
#define SM_BOFF  (2 * A_BUF)            // 37440
#define SMEM_SZ  (SM_BOFF + 3 * B_BUF)  // 92736 (x2 = 185472 <= 228KB/SM)

// Load A tile for dh: rows 1..128 <- w_in 0..127; rows 0,129 zeroed.
__device__ __forceinline__ void loadA(uint32_t abase, const __half* arr,
                                      int h, int dh, int tid) {
    const int hin = h + dh;
    if ((unsigned)hin < 128u) {
        if (tid < 18) {
            uint32_t adr = abase + ((tid < 9) ? 0u : (uint32_t)(129 * A_STRIDE))
                         + (uint32_t)(tid % 9) * 16u;
            st16z(adr);
        }
        const __half* rowp = arr + (size_t)hin * (WWID * C_IN);
#pragma unroll
        for (int i = 0; i < 4; ++i) {
            int idx = i * 256 + tid;           // 0..1023
            int r = idx >> 3, c = idx & 7;
            cpa16(abase + (uint32_t)(r + 1) * A_STRIDE + c * 16,
                  rowp + r * C_IN + c * 8);
        }
    } else {
#pragma unroll
        for (int i = 0; i < 5; ++i) {
            int idx = i * 256 + tid;
            if (idx < (A_BUF / 16)) st16z(abase + idx * 16);
        }
    }
}
__device__ __forceinline__ void loadB(uint32_t bbase, int kpos, int tid) {
    const __half* w = g_W + kpos * 8192;
#pragma unroll
    for (int i = 0; i < 4; ++i) {
        int idx = i * 256 + tid;               // 0..1023
        int f = idx >> 3, c = idx & 7;
        cpa16(bbase + (uint32_t)f * B_STRIDE + c * 16, w + f * 64 + c * 8);
    }
}

// Fragment loaders (per warp, 64x32 tile)
__device__ __forceinline__ void loadBfrag(uint32_t* bf, uint32_t bB, int ks) {
#pragma unroll
    for (int p2 = 0; p2 < 2; ++p2) {
        uint32_t r[4];
        ldsm4(r, bB + p2 * 16 * B_STRIDE + ks * 32);
        bf[p2 * 2]         = r[0];   // b0 even
        bf[4 + p2 * 2]     = r[1];   // b1 even
        bf[p2 * 2 + 1]     = r[2];   // b0 odd
        bf[4 + p2 * 2 + 1] = r[3];   // b1 odd
    }
}
__device__ __forceinline__ void loadAfrag(uint32_t* af, uint32_t aB, int ks) {
#pragma unroll
    for (int mi = 0; mi < 4; ++mi)
        ldsm4(af + mi * 4, aB + mi * 16 * A_STRIDE + ks * 32);
}

// ---------------- kernel 2: mma.sync conv (R14 engine + .cs stores) -------
__global__ void __launch_bounds__(256, 2)
conv_mma_kernel(const float* __restrict__ bias, float* __restrict__ out) {
    extern __shared__ char smem[];
    const uint32_t sb = s2u(smem);
    const int tid = threadIdx.x, wid = tid >> 5, l = tid & 31;
    const int m0w = (wid & 1) * 64, n0w = (wid >> 1) * 32;
    const int bx = blockIdx.x;
    const int n = bx >> 7, h = bx & 127;

    const __half* xh = g_xh + (size_t)n * (HH * WWID * C_IN);

    float acc[4][4][4];
#pragma unroll
    for (int mi = 0; mi < 4; ++mi)
#pragma unroll
        for (int ni = 0; ni < 4; ++ni)
#pragma unroll
            for (int c = 0; c < 4; ++c) acc[mi][ni][c] = 0.f;

    const uint32_t arow = (uint32_t)(m0w + (l & 15) + 1) * A_STRIDE + (l >> 4) * 16;
    const uint32_t brow = (uint32_t)(n0w + ((l >> 4) << 3) + (l & 7)) * B_STRIDE
                        + ((l >> 3) & 1) * 16;

    // prologue: G0 = A(dh=-1)->abuf0 + B0->bbuf0 ; G1 = B1->bbuf1
    loadA(sb, xh, h, -1, tid);
    loadB(sb + SM_BOFF, 0, tid);
    CP_COMMIT();
    loadB(sb + SM_BOFF + B_BUF, 1, tid);
    CP_COMMIT();

#pragma unroll 1
    for (int di = 0; di < 3; ++di) {
        const uint32_t aBase = sb + (di & 1) * A_BUF + arow;
#pragma unroll
        for (int j = 0; j < 3; ++j) {           // dw = j-1, k = di*3+j
            CP_WAIT1();                          // this k's A + B resident
            __syncthreads();                     // visibility + reuse safety

            const uint32_t aB = aBase + (j - 1) * A_STRIDE;
            const uint32_t bB = sb + SM_BOFF + j * B_BUF + brow;

            // early fragment warmup for ks=0
            uint32_t bf[2][8], af[2][16];
            loadBfrag(bf[0], bB, 0);
            loadAfrag(af[0], aB, 0);

            // issue future global loads (B: +2 iterations; A: +3)
            if (di < 2 || j == 0)
                loadB(sb + SM_BOFF + ((j + 2) % 3) * B_BUF, di * 3 + j + 2, tid);
            if (j == 0 && di < 2)
                loadA(sb + ((di + 1) & 1) * A_BUF, xh, h, di, tid);
            CP_COMMIT();

#pragma unroll
            for (int ks = 0; ks < 4; ++ks) {
                const int cur = ks & 1, nxt = cur ^ 1;
                if (ks < 3) {                    // prefetch next fragments
                    loadBfrag(bf[nxt], bB, ks + 1);
                    loadAfrag(af[nxt], aB, ks + 1);
                }
#pragma unroll
                for (int mi = 0; mi < 4; ++mi)
#pragma unroll
                    for (int ni = 0; ni < 4; ++ni)
                        mma16816(acc[mi][ni], &af[cur][mi * 4],
                                 bf[cur][ni], bf[cur][4 + ni]);
            }
        }
    }

    // epilogue: +bias, ReLU, streaming store
    float2 bb[4];
#pragma unroll
    for (int ni = 0; ni < 4; ++ni) {
        int col = n0w + ni * 8 + (l & 3) * 2;
        bb[ni] = *reinterpret_cast<const float2*>(bias + col);
    }
#pragma unroll
    for (int mi = 0; mi < 4; ++mi) {
#pragma unroll
        for (int ni = 0; ni < 4; ++ni) {
            int col = n0w + ni * 8 + (l & 3) * 2;
            size_t pix = (size_t)bx * 128 + m0w + mi * 16 + (l >> 2);
            stg2_cs(out + pix * F_OUT + col,
                    fmaxf(acc[mi][ni][0] + bb[ni].x, 0.f),
                    fmaxf(acc[mi][ni][1] + bb[ni].y, 0.f));
            stg2_cs(out + (pix + 8) * F_OUT + col,
                    fmaxf(acc[mi][ni][2] + bb[ni].x, 0.f),
                    fmaxf(acc[mi][ni][3] + bb[ni].y, 0.f));
        }
    }
}

// ---------------- launch ----------------
extern "C" void kernel_launch(void* const* d_in, const int* in_sizes, int n_in,
                              void* d_out, int out_size) {
    const float* x    = (const float*)d_in[0];
    const float* kern = (const float*)d_in[1];
    const float* b    = (const float*)d_in[2];
    const float* D    = (const float*)d_in[3];
    const float* u    = (const float*)d_in[4];
    float* out = (float*)d_out;

    static int smem_set = 0;
    if (!smem_set) {
        cudaFuncSetAttribute(conv_mma_kernel,
                             cudaFuncAttributeMaxDynamicSharedMemorySize, SMEM_SZ);
        smem_set = 1;
    }

    prep_kernel<<<32 + (NPIX * C_IN / 8) / 256, 256>>>(x, D, u, kern);
    conv_mma_kernel<<<NB * HH, 256, SMEM_SZ>>>(b, out);
}